// round 1
// baseline (speedup 1.0000x reference)
#include <cuda_runtime.h>
#include <math.h>

#define THREADS 256

// SpikeToCalciumDoubleExp: out[t] = sum_m (A1^(K-m) - A2^(K-m))/scale * u[t+m]
// Computed via two exact sliding geometric recursions:
//   S_a[t+1] = a*(S_a[t] + u[t+K]) - a^(K+1)*u[t]
// Each thread owns L consecutive outputs: one 121-tap warm-up dot, then L-1
// O(1) recursion steps. Input tile + output tile staged in shared memory for
// fully coalesced global traffic; odd L => conflict-free smem strides.
__global__ void __launch_bounds__(THREADS)
dexp_conv_kernel(const float* __restrict__ u, float* __restrict__ out,
                 int T_out, int T_in, int K, int T_chunk, int nchunks, int L,
                 int in_cap, int w_off,
                 float A1, float A2, float negC1, float invScale,
                 float inv_tau1, float inv_tau2)
{
    extern __shared__ float sm[];
    float*  sin_ = sm;                 // [in_cap]  input tile (padded to x4)
    float*  sout = sm + in_cap;        // [T_chunk] output tile (16B aligned)
    float2* w    = (float2*)(sm + w_off); // [K] weight table

    const int tid = threadIdx.x;
    const int row = blockIdx.x / nchunks;
    const int c   = blockIdx.x - row * nchunks;
    const int t0  = c * T_chunk;
    const int nout = min(T_chunk, T_out - t0);
    const int nin  = nout + K - 1;

    const float* g = u + (long long)row * T_in + t0;

    // ---- stage input tile (coalesced) ----
    for (int i = tid; i < nin; i += THREADS) sin_[i] = g[i];

    // ---- build weight table w[m] = (A1^(K-m), A2^(K-m)) ----
    for (int m = tid; m < K; m += THREADS) {
        float e = (float)(K - m);
        w[m] = make_float2(expf(-e * inv_tau1), expf(-e * inv_tau2));
    }
    __syncthreads();

    // ---- per-thread segment: warm-up dot + recursion ----
    const int b = tid * L;
    const int n = min(L, nout - b);
    if (n > 0) {
        float S1 = 0.0f, S2 = 0.0f;
        #pragma unroll 4
        for (int m = 0; m < K; ++m) {
            float  uu = sin_[b + m];
            float2 ww = w[m];
            S1 = fmaf(ww.x, uu, S1);
            S2 = fmaf(ww.y, uu, S2);
        }
        sout[b] = (S1 - S2) * invScale;

        #pragma unroll 4
        for (int i = 1; i < n; ++i) {
            float un = sin_[b + i - 1 + K];
            float uo = sin_[b + i - 1];
            S1 = fmaf(A1, S1 + un, negC1 * uo);   // exact window slide (slow exp)
            S2 = A2 * (S2 + un);                  // fast exp: a^(K+1) ~ 3e-27, dropped
            sout[b + i] = (S1 - S2) * invScale;
        }
    }
    __syncthreads();

    // ---- coalesced store of output tile ----
    float* go = out + (long long)row * T_out + t0;
    if (((T_out | t0 | nout) & 3) == 0) {
        float4*       go4 = (float4*)go;
        const float4* so4 = (const float4*)sout;   // sout is 16B-aligned (in_cap % 4 == 0)
        const int n4 = nout >> 2;
        for (int i = tid; i < n4; i += THREADS) go4[i] = so4[i];
    } else {
        for (int i = tid; i < nout; i += THREADS) go[i] = sout[i];
    }
}

extern "C" void kernel_launch(void* const* d_in, const int* in_sizes, int n_in,
                              void* d_out, int out_size)
{
    const float* u   = (const float*)d_in[0];
    float*       out = (float*)d_out;

    const int K = in_sizes[1];                       // 121
    const long long in0 = (long long)in_sizes[0];    // B*(T_out+K-1)
    const int B     = (int)((in0 - (long long)out_size) / (K - 1));  // 1024
    const int T_out = out_size / B;                  // 30000
    const int T_in  = T_out + K - 1;                 // 30121

    const int nchunks = 4;
    const int T_chunk = (T_out + nchunks - 1) / nchunks;   // 7500

    // smem layout (floats): [in_cap | T_chunk | pad | 2*K]
    const int in_cap = (T_chunk + K - 1 + 3) & ~3;         // pad to x4 -> sout 16B aligned
    int w_off = in_cap + T_chunk;
    w_off = (w_off + 1) & ~1;                              // float2 alignment
    const size_t smem = (size_t)(w_off + 2 * K) * sizeof(float);

    int L = (T_chunk + THREADS - 1) / THREADS;             // outputs per thread
    if ((L & 1) == 0) L++;                                 // odd => conflict-free smem

    // analytic constants (double precision on host)
    const double tau1 = 20.0, tau2 = 2.0;                  // TAU1*HZ, TAU2*HZ
    const double r = tau1 / tau2, d = tau1 - tau2;
    const double scale = pow(r, -tau2 / d) - pow(r, -tau1 / d);
    const float A1 = (float)exp(-1.0 / tau1);
    const float A2 = (float)exp(-1.0 / tau2);
    const float negC1 = (float)(-exp(-(double)(K + 1) / tau1));
    const float invScale = (float)(1.0 / scale);
    const float inv_tau1 = (float)(1.0 / tau1);
    const float inv_tau2 = (float)(1.0 / tau2);

    cudaFuncSetAttribute(dexp_conv_kernel,
                         cudaFuncAttributeMaxDynamicSharedMemorySize, (int)smem);

    dexp_conv_kernel<<<B * nchunks, THREADS, smem>>>(
        u, out, T_out, T_in, K, T_chunk, nchunks, L,
        in_cap, w_off, A1, A2, negC1, invScale, inv_tau1, inv_tau2);
}

// round 2
// speedup vs baseline: 1.0503x; 1.0503x over previous
#include <cuda_runtime.h>
#include <math.h>

#define THREADS 256
#define LSEG    32
#define KTAPS   121
#define KPART   25                         // KTAPS - 3*32
#define TCHUNK  (THREADS * LSEG)           // 8192
#define RAWCAP  (TCHUNK + KTAPS - 1)       // 8312 raw input floats per tile
#define TILECAP 8572                       // skew(8311)=8570, +pad, 16B-aligned
#define SOUTCAP 8448                       // skew(8191)=8446, +pad
#define NEXTRA  3
#define RBUFN   (THREADS + NEXTRA)         // 259 float4 slots (aliases sout)
#define SMEM_FLOATS (TILECAP + SOUTCAP)    // 17020 -> 68080 bytes

__device__ __forceinline__ int skewi(int i) { return i + (i >> 5); }

// Computes R = sum_{j<32} w^j u[32s+j] for w=1/A (register weight chain),
// with a 25-term prefix snapshot (q1,q2). tile is skew-addressed: for
// raw = 32s + j (j<32), skewed address = 33s + j (contiguous, stride-33
// across lanes => conflict-free).
__device__ __forceinline__ float4 seg_partials(const float* tile, int s,
                                               float invA1, float invA2)
{
    const float* p = tile + 33 * s;
    float r1 = 0.f, r2 = 0.f, w1 = 1.f, w2 = 1.f, q1, q2;
    #pragma unroll
    for (int j = 0; j < KPART; ++j) {
        float v = p[j];
        r1 = fmaf(w1, v, r1); r2 = fmaf(w2, v, r2);
        w1 *= invA1; w2 *= invA2;
    }
    q1 = r1; q2 = r2;
    #pragma unroll
    for (int j = KPART; j < 32; ++j) {
        float v = p[j];
        r1 = fmaf(w1, v, r1); r2 = fmaf(w2, v, r2);
        w1 *= invA1; w2 *= invA2;
    }
    return make_float4(r1, r2, q1, q2);
}

__global__ void __launch_bounds__(THREADS, 3)
dexp_scan_kernel(const float* __restrict__ u, float* __restrict__ out,
                 int T_out, int T_in, int nchunks,
                 float A1, float A2, float negC1, float invScale,
                 float invA1, float invA2,
                 float c11, float c21, float c31,
                 float c12, float c22, float c32,
                 float F1, float F2)
{
    extern __shared__ float sm[];
    float*  tile = sm;                       // [TILECAP] skewed input tile
    float*  sout = sm + TILECAP;             // [SOUTCAP] skewed output tile
    float4* rbuf = (float4*)(sm + TILECAP);  // aliases sout (dead after warm-up)

    const int tid = threadIdx.x;
    const int row = blockIdx.x / nchunks;
    const int c   = blockIdx.x - row * nchunks;
    const int t0  = c * TCHUNK;
    const int nout = min(TCHUNK, T_out - t0);
    const int nin  = nout + KTAPS - 1;

    // ---- stage input tile (full capacity, zero-fill tail => deterministic) ----
    const float* gin = u + (size_t)row * T_in + t0;
    for (int i = tid; i < RAWCAP; i += THREADS)
        tile[skewi(i)] = (i < nin) ? gin[i] : 0.0f;
    __syncthreads();

    // ---- per-segment geometric partials (register-chain weights, no table) ----
    float4 myR = seg_partials(tile, tid, invA1, invA2);
    rbuf[tid] = myR;
    if (tid < NEXTRA)
        rbuf[THREADS + tid] = seg_partials(tile, THREADS + tid, invA1, invA2);
    __syncthreads();

    // ---- combine: exact 121-tap window state at t = b = 32*tid ----
    float4 n1 = rbuf[tid + 1];
    float4 n2 = rbuf[tid + 2];
    float4 n3 = rbuf[tid + 3];
    float S1 = F1 * (((myR.x + c11 * n1.x) + c21 * n2.x) + c31 * n3.z);
    float S2 = F2 * (((myR.y + c12 * n1.y) + c22 * n2.y) + c32 * n3.w);
    __syncthreads();   // all rbuf reads done before sout overwrites the union

    // ---- sliding recursion: 32 outputs, fully unrolled (static smem offsets) ----
    {
        const float* base = tile + 33 * tid;   // skewed base of this segment
        float*       so   = sout + 33 * tid;   // skew(32*tid + g) = 33*tid + g
        #pragma unroll
        for (int g4 = 0; g4 < LSEG; g4 += 4) {
            #pragma unroll
            for (int j = 0; j < 4; ++j) {
                so[g4 + j] = (S1 - S2) * invScale;
                if (g4 + j != LSEG - 1) {      // folds at compile time
                    const int s_old = g4 + j;
                    const int s_new = s_old + KTAPS;
                    float un = base[s_new + (s_new >> 5)];
                    float uo = base[s_old];
                    S1 = fmaf(A1, S1 + un, negC1 * uo);  // exact window slide
                    S2 = A2 * (S2 + un);                 // exit term ~3e-27: dropped
                }
            }
        }
    }
    __syncthreads();

    // ---- coalesced store (skewed gather is stride-1 per warp: conflict-free) ----
    float* gout = out + (size_t)row * T_out + t0;
    for (int i = tid; i < nout; i += THREADS)
        gout[i] = sout[skewi(i)];
}

// Generic fallback (only used if K != 121; safety net for shape changes).
__global__ void dexp_fallback(const float* __restrict__ u,
                              const float* __restrict__ kern,
                              float* __restrict__ out,
                              int T_out, int T_in, int K)
{
    long long idx = (long long)blockIdx.x * blockDim.x + threadIdx.x;
    long long total = (long long)gridDim.y * T_out;
    (void)total;
    int row = blockIdx.y;
    int t = (int)idx;
    if (t >= T_out) return;
    const float* up = u + (size_t)row * T_in + t;
    float acc = 0.f;
    for (int j = 0; j < K; ++j) acc = fmaf(up[j], kern[K - 1 - j], acc);
    out[(size_t)row * T_out + t] = acc;
}

extern "C" void kernel_launch(void* const* d_in, const int* in_sizes, int n_in,
                              void* d_out, int out_size)
{
    const float* u    = (const float*)d_in[0];
    const float* kern = (const float*)d_in[1];
    float*       out  = (float*)d_out;

    const int K = in_sizes[1];
    const long long in0 = (long long)in_sizes[0];
    const int B     = (int)((in0 - (long long)out_size) / (K - 1));   // 1024
    const int T_out = out_size / B;                                   // 30000
    const int T_in  = T_out + K - 1;                                  // 30121

    if (K != KTAPS) {   // safety fallback, never taken for this dataset
        dim3 grid((T_out + 255) / 256, B);
        dexp_fallback<<<grid, 256>>>(u, kern, out, T_out, T_in, K);
        return;
    }

    const int nchunks = (T_out + TCHUNK - 1) / TCHUNK;   // 4

    // analytic constants in double precision
    const double tau1 = 20.0, tau2 = 2.0;
    const double r = tau1 / tau2, d = tau1 - tau2;
    const double scale = pow(r, -tau2 / d) - pow(r, -tau1 / d);

    const float A1     = (float)exp(-1.0 / tau1);
    const float A2     = (float)exp(-1.0 / tau2);
    const float invA1  = (float)exp(1.0 / tau1);
    const float invA2  = (float)exp(1.0 / tau2);
    const float negC1  = (float)(-exp(-(double)(KTAPS + 1) / tau1));
    const float invScale = (float)(1.0 / scale);
    const float F1  = (float)exp(-(double)KTAPS / tau1);
    const float F2  = (float)exp(-(double)KTAPS / tau2);
    const float c11 = (float)exp(32.0 / tau1);
    const float c21 = (float)exp(64.0 / tau1);
    const float c31 = (float)exp(96.0 / tau1);
    const float c12 = (float)exp(32.0 / tau2);
    const float c22 = (float)exp(64.0 / tau2);
    const float c32 = (float)exp(96.0 / tau2);

    const size_t smem = (size_t)SMEM_FLOATS * sizeof(float);   // 68080 B
    cudaFuncSetAttribute(dexp_scan_kernel,
                         cudaFuncAttributeMaxDynamicSharedMemorySize, (int)smem);

    dexp_scan_kernel<<<B * nchunks, THREADS, smem>>>(
        u, out, T_out, T_in, nchunks,
        A1, A2, negC1, invScale, invA1, invA2,
        c11, c21, c31, c12, c22, c32, F1, F2);
}